// round 3
// baseline (speedup 1.0000x reference)
#include <cuda_runtime.h>
#include <cstdint>

#define NN      100000
#define NE      1600000
#define HID     16
#define OUTD    40
#define QMAXF   255.0f

#define SCAN_BLOCKS 98          // ceil(NN/1024)
#define SCAT_BLOCKS 1563        // ceil(NE/4/256)
#define L1_BLOCKS   370         // layer1: 370*8 = 2960 warps
#define HIST_BLOCKS 1563

// ---------------------------------------------------------------------------
// Scratch (device globals — allocation is forbidden)
// ---------------------------------------------------------------------------
__device__ float g_ya[NN * HID];
__device__ float g_yb[NN * HID];
__device__ int2  g_ecv[NE];          // row-sorted (col, val-bits)
__device__ int   g_rank[NE];         // edge rank within its row
__device__ int   g_cnt[NN];
__device__ int   g_off[NN + 1];
__device__ int   g_pub[128];         // scan block aggregates (+1), 0 = not ready

// ---------------------------------------------------------------------------
// Hist + rank: rank[e] = postfix count of row[e]. 4 edges / thread.
// ---------------------------------------------------------------------------
__global__ void __launch_bounds__(256) k_hist(const int* __restrict__ row) {
    int t = blockIdx.x * 256 + threadIdx.x;
    int base = t * 4;
    if (base >= NE) return;
    int4 rr = __ldg(&((const int4*)row)[t]);
    int r0 = atomicAdd(&g_cnt[rr.x], 1);
    int r1 = atomicAdd(&g_cnt[rr.y], 1);
    int r2 = atomicAdd(&g_cnt[rr.z], 1);
    int r3 = atomicAdd(&g_cnt[rr.w], 1);
    ((int4*)g_rank)[t] = make_int4(r0, r1, r2, r3);
}

// ---------------------------------------------------------------------------
// Single-kernel exclusive scan of g_cnt -> g_off. 98 blocks (all wave-1
// resident), publish block aggregate, poll predecessors' aggregates.
// ---------------------------------------------------------------------------
__global__ void __launch_bounds__(256) k_scan() {
    const int b = blockIdx.x, t = threadIdx.x;
    const int base = b * 1024 + t * 4;

    int c[4], tot = 0;
#pragma unroll
    for (int i = 0; i < 4; i++) {
        int idx = base + i;
        c[i] = (idx < NN) ? g_cnt[idx] : 0;
        tot += c[i];
    }

    __shared__ int sh[256];
    sh[t] = tot; __syncthreads();
#pragma unroll
    for (int o = 1; o < 256; o <<= 1) {          // inclusive Hillis-Steele
        int u = (t >= o) ? sh[t - o] : 0;
        __syncthreads();
        sh[t] += u;
        __syncthreads();
    }
    const int exclThread = sh[t] - tot;
    const int blockTotal = sh[255];

    if (t == 0) atomicExch(&g_pub[b], blockTotal + 1);

    int predSum = 0;
    if (t < b) {                                  // poll predecessor t
        int v;
        do { v = atomicAdd(&g_pub[t], 0); } while (v == 0);
        predSum = v - 1;
    }
    __syncthreads();
    sh[t] = predSum; __syncthreads();
#pragma unroll
    for (int o = 128; o > 0; o >>= 1) {
        if (t < o) sh[t] += sh[t + o];
        __syncthreads();
    }
    int run = sh[0] + exclThread;                 // exclusive offset
#pragma unroll
    for (int i = 0; i < 4; i++) {
        int idx = base + i;
        if (idx < NN) { g_off[idx] = run; run += c[i]; }
    }
    if (b == SCAN_BLOCKS - 1 && t == 255) g_off[NN] = NE;
}

// ---------------------------------------------------------------------------
// Fused kernel: blocks [0, SCAT_BLOCKS) do the CSR scatter (atomic-free),
// blocks [SCAT_BLOCKS, +L1_BLOCKS) do layer-1 (128-dim qdq + @W1).
// Overlaps L2-store-bound scatter with DRAM-bound layer1.
// ---------------------------------------------------------------------------
template<int OFF, int V>
__device__ __forceinline__ void reduce_stage(float* acc, int lane) {
    const bool hi = (lane & OFF) != 0;
    float out[V];
#pragma unroll
    for (int m = 0; m < V; m++) {
        float keep = hi ? acc[m + V] : acc[m];
        float send = hi ? acc[m]     : acc[m + V];
        out[m] = keep + __shfl_xor_sync(0xffffffffu, send, OFF);
    }
#pragma unroll
    for (int m = 0; m < V; m++) acc[m] = out[m];
}

__global__ void __launch_bounds__(256) k_big(
    const int* __restrict__ row, const int* __restrict__ col,
    const float* __restrict__ vals,
    const float* __restrict__ x, const float* __restrict__ noise,
    const float* __restrict__ W1, float* __restrict__ y)
{
    if (blockIdx.x < SCAT_BLOCKS) {
        // ---- scatter: 4 edges / thread, no atomics ----
        int t = blockIdx.x * 256 + threadIdx.x;
        int base = t * 4;
        if (base >= NE) return;
        int4   rr = __ldg(&((const int4*)row)[t]);
        int4   cc = __ldg(&((const int4*)col)[t]);
        float4 vv = __ldg(&((const float4*)vals)[t]);
        int4   kk = __ldg(&((const int4*)g_rank)[t]);
        g_ecv[__ldg(&g_off[rr.x]) + kk.x] = make_int2(cc.x, __float_as_int(vv.x));
        g_ecv[__ldg(&g_off[rr.y]) + kk.y] = make_int2(cc.y, __float_as_int(vv.y));
        g_ecv[__ldg(&g_off[rr.z]) + kk.z] = make_int2(cc.z, __float_as_int(vv.z));
        g_ecv[__ldg(&g_off[rr.w]) + kk.w] = make_int2(cc.w, __float_as_int(vv.w));
        return;
    }

    // ---- layer1: warp per row, W1 register-resident ----
    const int lane   = threadIdx.x & 31;
    const int warpId = (blockIdx.x - SCAT_BLOCKS) * 8 + (threadIdx.x >> 5);
    const int nWarp  = L1_BLOCKS * 8;

    float4 w[16];
    const float4* W4 = (const float4*)W1;
#pragma unroll
    for (int i = 0; i < 4; i++)
#pragma unroll
        for (int jj = 0; jj < 4; jj++)
            w[i * 4 + jj] = __ldg(&W4[(lane * 4 + i) * 4 + jj]);

    for (int r = warpId; r < NN; r += nWarp) {
        float4 xv = __ldg(&((const float4*)x)[r * 32 + lane]);
        float4 nv = __ldg(&((const float4*)noise)[r * 32 + lane]);
        float xa[4] = {xv.x, xv.y, xv.z, xv.w};
        float na[4] = {nv.x, nv.y, nv.z, nv.w};

        float mn = fminf(fminf(xa[0], xa[1]), fminf(xa[2], xa[3]));
        float mx = fmaxf(fmaxf(xa[0], xa[1]), fmaxf(xa[2], xa[3]));
#pragma unroll
        for (int off = 16; off > 0; off >>= 1) {
            mn = fminf(mn, __shfl_xor_sync(0xffffffffu, mn, off));
            mx = fmaxf(mx, __shfl_xor_sync(0xffffffffu, mx, off));
        }

        float dq[4];
        if (mx > mn) {
            float rs = QMAXF / (mx - mn);
#pragma unroll
            for (int i = 0; i < 4; i++) {
                float q = rintf((xa[i] - mn) * rs + na[i] - 0.5f);
                q = fminf(fmaxf(q, 0.f), QMAXF);
                dq[i] = q / rs + mn;
            }
        } else {
#pragma unroll
            for (int i = 0; i < 4; i++) dq[i] = mn;
        }

        float acc[16];
#pragma unroll
        for (int j = 0; j < 16; j++) acc[j] = 0.f;
#pragma unroll
        for (int i = 0; i < 4; i++) {
#pragma unroll
            for (int jj = 0; jj < 4; jj++) {
                float4 ww = w[i * 4 + jj];
                acc[jj * 4 + 0] = fmaf(dq[i], ww.x, acc[jj * 4 + 0]);
                acc[jj * 4 + 1] = fmaf(dq[i], ww.y, acc[jj * 4 + 1]);
                acc[jj * 4 + 2] = fmaf(dq[i], ww.z, acc[jj * 4 + 2]);
                acc[jj * 4 + 3] = fmaf(dq[i], ww.w, acc[jj * 4 + 3]);
            }
        }
        reduce_stage<16, 8>(acc, lane);
        reduce_stage<8, 4>(acc, lane);
        reduce_stage<4, 2>(acc, lane);
        reduce_stage<2, 1>(acc, lane);
        float s = acc[0] + __shfl_xor_sync(0xffffffffu, acc[0], 1);
        if ((lane & 1) == 0)
            y[r * 16 + ((lane >> 1) & 15)] = s;
    }
}

// ---------------------------------------------------------------------------
// CSR row-gather SpMM, half-warp (16 lanes = 16 dims) per row, fused epilogue.
//   EP=1: relu+qdq+@W(16x16) -> y    EP=2: relu+qdq -> y    EP=3: @W3 -> out
// ---------------------------------------------------------------------------
template<int EP>
__global__ void __launch_bounds__(256) k_spmm(
    const float* __restrict__ yin, const float* __restrict__ noise,
    const float* __restrict__ W, float* __restrict__ out)
{
    __shared__ float Ws[16 * 40];
    if (EP == 1) Ws[threadIdx.x] = W[threadIdx.x];
    if (EP == 3) { for (int i = threadIdx.x; i < 640; i += 256) Ws[i] = W[i]; }
    if (EP != 2) __syncthreads();

    const int lane = threadIdx.x & 31;
    const int l    = lane & 15;
    const int r    = (blockIdx.x * 8 + (threadIdx.x >> 5)) * 2 + (lane >> 4);

    int       i = __ldg(&g_off[r]);
    const int e = __ldg(&g_off[r + 1]);
    float acc = 0.f;

    for (; i + 3 < e; i += 4) {
        int2 c0 = __ldg(&g_ecv[i]);
        int2 c1 = __ldg(&g_ecv[i + 1]);
        int2 c2 = __ldg(&g_ecv[i + 2]);
        int2 c3 = __ldg(&g_ecv[i + 3]);
        float y0 = __ldg(&yin[c0.x * 16 + l]);
        float y1 = __ldg(&yin[c1.x * 16 + l]);
        float y2 = __ldg(&yin[c2.x * 16 + l]);
        float y3 = __ldg(&yin[c3.x * 16 + l]);
        acc = fmaf(__int_as_float(c0.y), y0, acc);
        acc = fmaf(__int_as_float(c1.y), y1, acc);
        acc = fmaf(__int_as_float(c2.y), y2, acc);
        acc = fmaf(__int_as_float(c3.y), y3, acc);
    }
    for (; i < e; i++) {
        int2 cv = __ldg(&g_ecv[i]);
        acc = fmaf(__int_as_float(cv.y), __ldg(&yin[cv.x * 16 + l]), acc);
    }

    if (EP == 3) {
        float a0 = 0.f, a1 = 0.f, a2 = 0.f;
#pragma unroll
        for (int j = 0; j < 16; j++) {
            float d = __shfl_sync(0xffffffffu, acc, (lane & 16) + j);
            a0 = fmaf(d, Ws[j * 40 + l], a0);
            a1 = fmaf(d, Ws[j * 40 + l + 16], a1);
            if (l < 8) a2 = fmaf(d, Ws[j * 40 + l + 32], a2);
        }
        out[r * 40 + l]      = a0;
        out[r * 40 + l + 16] = a1;
        if (l < 8) out[r * 40 + l + 32] = a2;
    } else {
        float xr = fmaxf(acc, 0.f);
        float mn = xr, mx = xr;
#pragma unroll
        for (int o = 8; o > 0; o >>= 1) {
            mn = fminf(mn, __shfl_xor_sync(0xffffffffu, mn, o));
            mx = fmaxf(mx, __shfl_xor_sync(0xffffffffu, mx, o));
        }
        float dq;
        if (mx > mn) {
            float rs = QMAXF / (mx - mn);
            float nz = __ldg(&noise[r * 16 + l]);
            float q  = rintf((xr - mn) * rs + nz - 0.5f);
            q = fminf(fmaxf(q, 0.f), QMAXF);
            dq = q / rs + mn;
        } else dq = mn;

        if (EP == 2) {
            out[r * 16 + l] = dq;
        } else {
            float a = 0.f;
#pragma unroll
            for (int j = 0; j < 16; j++) {
                float d = __shfl_sync(0xffffffffu, dq, (lane & 16) + j);
                a = fmaf(d, Ws[j * 16 + l], a);
            }
            out[r * 16 + l] = a;
        }
    }
}

// ---------------------------------------------------------------------------
extern "C" void kernel_launch(void* const* d_in, const int* in_sizes, int n_in,
                              void* d_out, int out_size)
{
    const float* features = (const float*)d_in[0];
    const int*   row      = (const int*)  d_in[1];
    const int*   col      = (const int*)  d_in[2];
    const float* vals     = (const float*)d_in[3];
    const float* W1       = (const float*)d_in[4];
    const float* W2       = (const float*)d_in[5];
    const float* W3       = (const float*)d_in[6];
    const float* noise1   = (const float*)d_in[7];
    const float* noise2   = (const float*)d_in[8];
    const float* noise3   = (const float*)d_in[9];

    float *pya, *pyb; int *pcnt, *ppub;
    cudaGetSymbolAddress((void**)&pya,  g_ya);
    cudaGetSymbolAddress((void**)&pyb,  g_yb);
    cudaGetSymbolAddress((void**)&pcnt, g_cnt);
    cudaGetSymbolAddress((void**)&ppub, g_pub);

    cudaMemsetAsync(pcnt, 0, NN * sizeof(int));
    cudaMemsetAsync(ppub, 0, 128 * sizeof(int));

    k_hist<<<HIST_BLOCKS, 256>>>(row);
    k_scan<<<SCAN_BLOCKS, 256>>>();
    k_big <<<SCAT_BLOCKS + L1_BLOCKS, 256>>>(row, col, vals,
                                             features, noise1, W1, pya);

    k_spmm<1><<<NN / 16, 256>>>(pya, noise2, W2, pyb);
    k_spmm<2><<<NN / 16, 256>>>(pyb, noise3, nullptr, pya);
    k_spmm<3><<<NN / 16, 256>>>(pya, nullptr, W3, (float*)d_out);
}

// round 4
// speedup vs baseline: 1.0875x; 1.0875x over previous
#include <cuda_runtime.h>
#include <cstdint>

#define NN      100000
#define NE      1600000
#define HID     16
#define OUTD    40
#define QMAXF   255.0f

// ---------------------------------------------------------------------------
// Scratch (device globals — allocation is forbidden)
// ---------------------------------------------------------------------------
__device__ float g_ya[NN * HID];
__device__ float g_yb[NN * HID];
__device__ int2  g_ecv[NE];             // row-sorted (col, val-bits)
__device__ int   g_cnt[NN];
__device__ int   g_cur[NN];
__device__ int   g_off[NN + 1];
__device__ int   g_bsum[128];
__device__ int   g_boff[128];

// ---------------------------------------------------------------------------
// CSR build (R2 structure, measured good): clear -> hist -> scan x3 -> scatter
// ---------------------------------------------------------------------------
__global__ void __launch_bounds__(256) k_clear() {
    int t = blockIdx.x * 256 + threadIdx.x;
    if (t < NN) g_cnt[t] = 0;
}

__global__ void __launch_bounds__(256) k_hist(const int* __restrict__ row) {
    int e = blockIdx.x * 256 + threadIdx.x;
    if (e < NE) atomicAdd(&g_cnt[__ldg(&row[e])], 1);
}

__global__ void __launch_bounds__(256) k_scan1() {
    int b = blockIdx.x, t = threadIdx.x;
    int base = b * 1024 + t * 4;
    int s = 0;
#pragma unroll
    for (int i = 0; i < 4; i++) { int idx = base + i; if (idx < NN) s += g_cnt[idx]; }
    __shared__ int sh[256];
    sh[t] = s; __syncthreads();
#pragma unroll
    for (int o = 128; o > 0; o >>= 1) {
        if (t < o) sh[t] += sh[t + o];
        __syncthreads();
    }
    if (t == 0) g_bsum[b] = sh[0];
}

__global__ void __launch_bounds__(128) k_scan2() {
    int t = threadIdx.x;
    int v = (t < 98) ? g_bsum[t] : 0;
    __shared__ int sh[128];
    sh[t] = v; __syncthreads();
#pragma unroll
    for (int o = 1; o < 128; o <<= 1) {
        int u = (t >= o) ? sh[t - o] : 0;
        __syncthreads();
        sh[t] += u;
        __syncthreads();
    }
    if (t < 98) g_boff[t] = sh[t] - v;
}

__global__ void __launch_bounds__(256) k_scan3() {
    int b = blockIdx.x, t = threadIdx.x;
    int base = b * 1024 + t * 4;
    int c[4]; int tot = 0;
#pragma unroll
    for (int i = 0; i < 4; i++) {
        int idx = base + i;
        c[i] = (idx < NN) ? g_cnt[idx] : 0;
        tot += c[i];
    }
    __shared__ int sh[256];
    sh[t] = tot; __syncthreads();
#pragma unroll
    for (int o = 1; o < 256; o <<= 1) {
        int u = (t >= o) ? sh[t - o] : 0;
        __syncthreads();
        sh[t] += u;
        __syncthreads();
    }
    int run = sh[t] - tot + g_boff[b];
#pragma unroll
    for (int i = 0; i < 4; i++) {
        int idx = base + i;
        if (idx < NN) { g_off[idx] = run; g_cur[idx] = run; run += c[i]; }
    }
    if (b == 0 && t == 0) g_off[NN] = NE;
}

__global__ void __launch_bounds__(256) k_scatter(
    const int* __restrict__ row, const int* __restrict__ col,
    const float* __restrict__ vals)
{
    int e = blockIdx.x * 256 + threadIdx.x;
    if (e >= NE) return;
    int r = __ldg(&row[e]);
    int p = atomicAdd(&g_cur[r], 1);
    g_ecv[p] = make_int2(__ldg(&col[e]), __float_as_int(__ldg(&vals[e])));
}

// ---------------------------------------------------------------------------
// Layer 1: per-row (128-dim) qdq fused with x @ W1 -> y [N,16]. Warp per row.
// ---------------------------------------------------------------------------
template<int OFF, int V>
__device__ __forceinline__ void reduce_stage(float* acc, int lane) {
    const bool hi = (lane & OFF) != 0;
    float out[V];
#pragma unroll
    for (int m = 0; m < V; m++) {
        float keep = hi ? acc[m + V] : acc[m];
        float send = hi ? acc[m]     : acc[m + V];
        out[m] = keep + __shfl_xor_sync(0xffffffffu, send, OFF);
    }
#pragma unroll
    for (int m = 0; m < V; m++) acc[m] = out[m];
}

__global__ void __launch_bounds__(128) k_layer1(
    const float* __restrict__ x, const float* __restrict__ noise,
    const float* __restrict__ W1, float* __restrict__ y)
{
    const int lane   = threadIdx.x & 31;
    const int warpId = (blockIdx.x * (blockDim.x >> 5)) + (threadIdx.x >> 5);
    const int nWarp  = gridDim.x * (blockDim.x >> 5);

    float4 w[16];
    const float4* W4 = (const float4*)W1;
#pragma unroll
    for (int i = 0; i < 4; i++)
#pragma unroll
        for (int jj = 0; jj < 4; jj++)
            w[i * 4 + jj] = __ldg(&W4[(lane * 4 + i) * 4 + jj]);

    for (int r = warpId; r < NN; r += nWarp) {
        float4 xv = __ldg(&((const float4*)x)[r * 32 + lane]);
        float4 nv = __ldg(&((const float4*)noise)[r * 32 + lane]);
        float xa[4] = {xv.x, xv.y, xv.z, xv.w};
        float na[4] = {nv.x, nv.y, nv.z, nv.w};

        float mn = fminf(fminf(xa[0], xa[1]), fminf(xa[2], xa[3]));
        float mx = fmaxf(fmaxf(xa[0], xa[1]), fmaxf(xa[2], xa[3]));
#pragma unroll
        for (int off = 16; off > 0; off >>= 1) {
            mn = fminf(mn, __shfl_xor_sync(0xffffffffu, mn, off));
            mx = fmaxf(mx, __shfl_xor_sync(0xffffffffu, mx, off));
        }

        float dq[4];
        if (mx > mn) {
            float rs = QMAXF / (mx - mn);
#pragma unroll
            for (int i = 0; i < 4; i++) {
                float q = rintf((xa[i] - mn) * rs + na[i] - 0.5f);
                q = fminf(fmaxf(q, 0.f), QMAXF);
                dq[i] = q / rs + mn;
            }
        } else {
#pragma unroll
            for (int i = 0; i < 4; i++) dq[i] = mn;
        }

        float acc[16];
#pragma unroll
        for (int j = 0; j < 16; j++) acc[j] = 0.f;
#pragma unroll
        for (int i = 0; i < 4; i++) {
#pragma unroll
            for (int jj = 0; jj < 4; jj++) {
                float4 ww = w[i * 4 + jj];
                acc[jj * 4 + 0] = fmaf(dq[i], ww.x, acc[jj * 4 + 0]);
                acc[jj * 4 + 1] = fmaf(dq[i], ww.y, acc[jj * 4 + 1]);
                acc[jj * 4 + 2] = fmaf(dq[i], ww.z, acc[jj * 4 + 2]);
                acc[jj * 4 + 3] = fmaf(dq[i], ww.w, acc[jj * 4 + 3]);
            }
        }
        reduce_stage<16, 8>(acc, lane);
        reduce_stage<8, 4>(acc, lane);
        reduce_stage<4, 2>(acc, lane);
        reduce_stage<2, 1>(acc, lane);
        float s = acc[0] + __shfl_xor_sync(0xffffffffu, acc[0], 1);
        if ((lane & 1) == 0)
            y[r * 16 + ((lane >> 1) & 15)] = s;
    }
}

// ---------------------------------------------------------------------------
// CSR row-gather SpMM: ONE WARP PER ROW. Edge pairs loaded as broadcast int4
// (2 edges / LDG); the two 16-lane halves take alternating pairs of the same
// row (uniform trip count). Halves combined with one shfl_xor(16).
//   EP=1: relu+qdq+@W(16x16) -> y    EP=2: relu+qdq -> y    EP=3: @W3 -> out
// Grid: NN/8 blocks x 8 warps = 100000 rows.
// ---------------------------------------------------------------------------
template<int EP>
__global__ void __launch_bounds__(256) k_spmm(
    const float* __restrict__ yin, const float* __restrict__ noise,
    const float* __restrict__ W, float* __restrict__ out)
{
    __shared__ float Ws[16 * 40];
    if (EP == 1) Ws[threadIdx.x] = W[threadIdx.x];
    if (EP == 3) { for (int i = threadIdx.x; i < 640; i += 256) Ws[i] = W[i]; }
    if (EP != 2) __syncthreads();

    const int lane = threadIdx.x & 31;
    const int l    = lane & 15;              // dim
    const int h    = lane >> 4;              // half id
    const int r    = blockIdx.x * 8 + (threadIdx.x >> 5);

    int       s = __ldg(&g_off[r]);
    const int e = __ldg(&g_off[r + 1]);
    float acc = 0.f;

    // peel to even start (half 0 only, so the sum isn't duplicated)
    if (s & 1) {
        if (s < e && h == 0) {
            int2 cv = __ldg(&g_ecv[s]);
            acc = fmaf(__int_as_float(cv.y), __ldg(&yin[cv.x * 16 + l]), acc);
        }
        s++;
    }
    if (s < e) {
        const int np = (e - s) >> 1;         // full pairs
        const int4* base = (const int4*)(g_ecv + s);
        for (int j = h; j < np; j += 2) {    // half h takes pairs h, h+2, ...
            int4 p = __ldg(&base[j]);        // edges (p.x,p.y) and (p.z,p.w)
            float ya = __ldg(&yin[p.x * 16 + l]);
            float yb = __ldg(&yin[p.z * 16 + l]);
            acc = fmaf(__int_as_float(p.y), ya, acc);
            acc = fmaf(__int_as_float(p.w), yb, acc);
        }
        int rem = s + np * 2;                // trailing odd edge
        if (rem < e && h == 0) {
            int2 cv = __ldg(&g_ecv[rem]);
            acc = fmaf(__int_as_float(cv.y), __ldg(&yin[cv.x * 16 + l]), acc);
        }
    }
    // combine halves: every lane now holds z[r][l]
    acc += __shfl_xor_sync(0xffffffffu, acc, 16);

    if (EP == 3) {
        float a0 = 0.f, a1 = 0.f;
#pragma unroll
        for (int j = 0; j < 16; j++) {
            float d = __shfl_sync(0xffffffffu, acc, j);
            a0 = fmaf(d, Ws[j * 40 + lane], a0);
            if (lane < 8) a1 = fmaf(d, Ws[j * 40 + 32 + lane], a1);
        }
        out[r * 40 + lane] = a0;
        if (lane < 8) out[r * 40 + 32 + lane] = a1;
    } else {
        float xr = fmaxf(acc, 0.f);
        float mn = xr, mx = xr;
#pragma unroll
        for (int o = 8; o > 0; o >>= 1) {    // min/max over the 16 dims
            mn = fminf(mn, __shfl_xor_sync(0xffffffffu, mn, o));
            mx = fmaxf(mx, __shfl_xor_sync(0xffffffffu, mx, o));
        }
        float dq;
        if (mx > mn) {
            float rs = QMAXF / (mx - mn);
            float nz = __ldg(&noise[r * 16 + l]);
            float q  = rintf((xr - mn) * rs + nz - 0.5f);
            q = fminf(fmaxf(q, 0.f), QMAXF);
            dq = q / rs + mn;
        } else dq = mn;

        if (EP == 2) {
            if (lane < 16) out[r * 16 + l] = dq;
        } else {
            float a = 0.f;
#pragma unroll
            for (int j = 0; j < 16; j++) {
                float d = __shfl_sync(0xffffffffu, dq, j);
                a = fmaf(d, Ws[j * 16 + l], a);
            }
            if (lane < 16) out[r * 16 + l] = a;
        }
    }
}

// ---------------------------------------------------------------------------
extern "C" void kernel_launch(void* const* d_in, const int* in_sizes, int n_in,
                              void* d_out, int out_size)
{
    const float* features = (const float*)d_in[0];
    const int*   row      = (const int*)  d_in[1];
    const int*   col      = (const int*)  d_in[2];
    const float* vals     = (const float*)d_in[3];
    const float* W1       = (const float*)d_in[4];
    const float* W2       = (const float*)d_in[5];
    const float* W3       = (const float*)d_in[6];
    const float* noise1   = (const float*)d_in[7];
    const float* noise2   = (const float*)d_in[8];
    const float* noise3   = (const float*)d_in[9];

    float *pya, *pyb;
    cudaGetSymbolAddress((void**)&pya, g_ya);
    cudaGetSymbolAddress((void**)&pyb, g_yb);

    const int nodeBlocks = (NN + 255) / 256;     // 391
    const int edgeBlocks = (NE + 255) / 256;     // 6250
    const int scanBlocks = (NN + 1023) / 1024;   // 98

    // CSR build (R2 structure)
    k_clear  <<<nodeBlocks, 256>>>();
    k_hist   <<<edgeBlocks, 256>>>(row);
    k_scan1  <<<scanBlocks, 256>>>();
    k_scan2  <<<1, 128>>>();
    k_scan3  <<<scanBlocks, 256>>>();
    k_scatter<<<edgeBlocks, 256>>>(row, col, vals);

    // Layer 1 dense front
    k_layer1<<<740, 128>>>(features, noise1, W1, pya);

    // SpMM pipeline: warp per row, 12500 blocks x 8 warps
    k_spmm<1><<<NN / 8, 256>>>(pya, noise2, W2, pyb);
    k_spmm<2><<<NN / 8, 256>>>(pyb, noise3, nullptr, pya);
    k_spmm<3><<<NN / 8, 256>>>(pya, nullptr, W3, (float*)d_out);
}

// round 5
// speedup vs baseline: 1.2318x; 1.1326x over previous
#include <cuda_runtime.h>
#include <cstdint>

#define NN      100000
#define NE      1600000
#define HID     16
#define OUTD    40
#define QMAXF   255.0f

// ---------------------------------------------------------------------------
// Scratch (device globals — allocation is forbidden)
// ---------------------------------------------------------------------------
__device__ float g_ya[NN * HID];
__device__ float g_yb[NN * HID];
__device__ __align__(16) int2 g_ecv[NE];   // row-sorted (col, val-bits)
__device__ int   g_cnt[NN];
__device__ int   g_cur[NN];
__device__ int   g_off[NN + 1];
__device__ int   g_bsum[128];

// ---------------------------------------------------------------------------
// CSR build: clear -> hist -> scan1 -> scan3(with folded base sum) -> scatter
// ---------------------------------------------------------------------------
__global__ void __launch_bounds__(256) k_clear() {
    int t = blockIdx.x * 256 + threadIdx.x;
    if (t < NN) g_cnt[t] = 0;
}

__global__ void __launch_bounds__(256) k_hist(const int* __restrict__ row) {
    int e = blockIdx.x * 256 + threadIdx.x;
    if (e < NE) atomicAdd(&g_cnt[__ldg(&row[e])], 1);
}

__global__ void __launch_bounds__(256) k_scan1() {
    int b = blockIdx.x, t = threadIdx.x;
    int base = b * 1024 + t * 4;
    int s = 0;
#pragma unroll
    for (int i = 0; i < 4; i++) { int idx = base + i; if (idx < NN) s += g_cnt[idx]; }
    __shared__ int sh[256];
    sh[t] = s; __syncthreads();
#pragma unroll
    for (int o = 128; o > 0; o >>= 1) {
        if (t < o) sh[t] += sh[t + o];
        __syncthreads();
    }
    if (t == 0) g_bsum[b] = sh[0];
}

// scan3: per-block exclusive scan of counts + predecessor base computed here
// (reduction over g_bsum[0..b)) — k_scan2 eliminated.
__global__ void __launch_bounds__(256) k_scan3() {
    int b = blockIdx.x, t = threadIdx.x;
    int base = b * 1024 + t * 4;
    int c[4]; int tot = 0;
#pragma unroll
    for (int i = 0; i < 4; i++) {
        int idx = base + i;
        c[i] = (idx < NN) ? g_cnt[idx] : 0;
        tot += c[i];
    }
    __shared__ int sh[256];
    sh[t] = tot; __syncthreads();
#pragma unroll
    for (int o = 1; o < 256; o <<= 1) {
        int u = (t >= o) ? sh[t - o] : 0;
        __syncthreads();
        sh[t] += u;
        __syncthreads();
    }
    const int exclThread = sh[t] - tot;
    __syncthreads();

    // predecessor base: sum g_bsum[0..b)
    sh[t] = (t < b) ? g_bsum[t] : 0;
    __syncthreads();
#pragma unroll
    for (int o = 128; o > 0; o >>= 1) {
        if (t < o) sh[t] += sh[t + o];
        __syncthreads();
    }
    int run = sh[0] + exclThread;
#pragma unroll
    for (int i = 0; i < 4; i++) {
        int idx = base + i;
        if (idx < NN) { g_off[idx] = run; g_cur[idx] = run; run += c[i]; }
    }
    if (b == 0 && t == 0) g_off[NN] = NE;
}

__global__ void __launch_bounds__(256) k_scatter(
    const int* __restrict__ row, const int* __restrict__ col,
    const float* __restrict__ vals)
{
    int e = blockIdx.x * 256 + threadIdx.x;
    if (e >= NE) return;
    int r = __ldg(&row[e]);
    int p = atomicAdd(&g_cur[r], 1);
    g_ecv[p] = make_int2(__ldg(&col[e]), __float_as_int(__ldg(&vals[e])));
}

// ---------------------------------------------------------------------------
// Layer 1: per-row (128-dim) qdq fused with x @ W1 -> y [N,16]. Warp per row.
// ---------------------------------------------------------------------------
template<int OFF, int V>
__device__ __forceinline__ void reduce_stage(float* acc, int lane) {
    const bool hi = (lane & OFF) != 0;
    float out[V];
#pragma unroll
    for (int m = 0; m < V; m++) {
        float keep = hi ? acc[m + V] : acc[m];
        float send = hi ? acc[m]     : acc[m + V];
        out[m] = keep + __shfl_xor_sync(0xffffffffu, send, OFF);
    }
#pragma unroll
    for (int m = 0; m < V; m++) acc[m] = out[m];
}

__global__ void __launch_bounds__(128) k_layer1(
    const float* __restrict__ x, const float* __restrict__ noise,
    const float* __restrict__ W1, float* __restrict__ y)
{
    const int lane   = threadIdx.x & 31;
    const int warpId = (blockIdx.x * (blockDim.x >> 5)) + (threadIdx.x >> 5);
    const int nWarp  = gridDim.x * (blockDim.x >> 5);

    float4 w[16];
    const float4* W4 = (const float4*)W1;
#pragma unroll
    for (int i = 0; i < 4; i++)
#pragma unroll
        for (int jj = 0; jj < 4; jj++)
            w[i * 4 + jj] = __ldg(&W4[(lane * 4 + i) * 4 + jj]);

    for (int r = warpId; r < NN; r += nWarp) {
        float4 xv = __ldg(&((const float4*)x)[r * 32 + lane]);
        float4 nv = __ldg(&((const float4*)noise)[r * 32 + lane]);
        float xa[4] = {xv.x, xv.y, xv.z, xv.w};
        float na[4] = {nv.x, nv.y, nv.z, nv.w};

        float mn = fminf(fminf(xa[0], xa[1]), fminf(xa[2], xa[3]));
        float mx = fmaxf(fmaxf(xa[0], xa[1]), fmaxf(xa[2], xa[3]));
#pragma unroll
        for (int off = 16; off > 0; off >>= 1) {
            mn = fminf(mn, __shfl_xor_sync(0xffffffffu, mn, off));
            mx = fmaxf(mx, __shfl_xor_sync(0xffffffffu, mx, off));
        }

        float dq[4];
        if (mx > mn) {
            float rs = QMAXF / (mx - mn);
#pragma unroll
            for (int i = 0; i < 4; i++) {
                float q = rintf((xa[i] - mn) * rs + na[i] - 0.5f);
                q = fminf(fmaxf(q, 0.f), QMAXF);
                dq[i] = q / rs + mn;
            }
        } else {
#pragma unroll
            for (int i = 0; i < 4; i++) dq[i] = mn;
        }

        float acc[16];
#pragma unroll
        for (int j = 0; j < 16; j++) acc[j] = 0.f;
#pragma unroll
        for (int i = 0; i < 4; i++) {
#pragma unroll
            for (int jj = 0; jj < 4; jj++) {
                float4 ww = w[i * 4 + jj];
                acc[jj * 4 + 0] = fmaf(dq[i], ww.x, acc[jj * 4 + 0]);
                acc[jj * 4 + 1] = fmaf(dq[i], ww.y, acc[jj * 4 + 1]);
                acc[jj * 4 + 2] = fmaf(dq[i], ww.z, acc[jj * 4 + 2]);
                acc[jj * 4 + 3] = fmaf(dq[i], ww.w, acc[jj * 4 + 3]);
            }
        }
        reduce_stage<16, 8>(acc, lane);
        reduce_stage<8, 4>(acc, lane);
        reduce_stage<4, 2>(acc, lane);
        reduce_stage<2, 1>(acc, lane);
        float s = acc[0] + __shfl_xor_sync(0xffffffffu, acc[0], 1);
        if ((lane & 1) == 0)
            y[r * 16 + ((lane >> 1) & 15)] = s;
    }
}

// ---------------------------------------------------------------------------
// CSR row-gather SpMM (R2 scheme): half-warp (16 lanes = 16 dims) per row,
// 4 edges per iteration, edges loaded as 2x int4 (2 edges per LDG.128).
//   EP=1: relu+qdq+@W(16x16) -> y    EP=2: relu+qdq -> y    EP=3: @W3 -> out
// Grid: 6250 blocks x 8 warps x 2 rows = 100000 rows.
// ---------------------------------------------------------------------------
template<int EP>
__global__ void __launch_bounds__(256) k_spmm(
    const float* __restrict__ yin, const float* __restrict__ noise,
    const float* __restrict__ W, float* __restrict__ out)
{
    __shared__ float Ws[16 * 40];
    if (EP == 1) Ws[threadIdx.x] = W[threadIdx.x];
    if (EP == 3) { for (int i = threadIdx.x; i < 640; i += 256) Ws[i] = W[i]; }
    if (EP != 2) __syncthreads();

    const int lane = threadIdx.x & 31;
    const int l    = lane & 15;                       // dim index
    const int r    = (blockIdx.x * 8 + (threadIdx.x >> 5)) * 2 + (lane >> 4);

    int       s = __ldg(&g_off[r]);
    const int e = __ldg(&g_off[r + 1]);
    float acc = 0.f;

    // peel to even start so int4 loads are 16B-aligned
    if ((s & 1) && s < e) {
        int2 cv = __ldg(&g_ecv[s]);
        acc = fmaf(__int_as_float(cv.y), __ldg(&yin[cv.x * 16 + l]), acc);
        s++;
    }
    {
        const int np = (e - s) >> 1;                  // full pairs
        const int4* base = (const int4*)(g_ecv + s);
        int j = 0;
        for (; j + 1 < np; j += 2) {                  // 4 edges / iter
            int4 p0 = __ldg(&base[j]);
            int4 p1 = __ldg(&base[j + 1]);
            float y0 = __ldg(&yin[p0.x * 16 + l]);
            float y1 = __ldg(&yin[p0.z * 16 + l]);
            float y2 = __ldg(&yin[p1.x * 16 + l]);
            float y3 = __ldg(&yin[p1.z * 16 + l]);
            acc = fmaf(__int_as_float(p0.y), y0, acc);
            acc = fmaf(__int_as_float(p0.w), y1, acc);
            acc = fmaf(__int_as_float(p1.y), y2, acc);
            acc = fmaf(__int_as_float(p1.w), y3, acc);
        }
        if (j < np) {                                 // last pair
            int4 p = __ldg(&base[j]);
            float y0 = __ldg(&yin[p.x * 16 + l]);
            float y1 = __ldg(&yin[p.z * 16 + l]);
            acc = fmaf(__int_as_float(p.y), y0, acc);
            acc = fmaf(__int_as_float(p.w), y1, acc);
        }
        int rem = s + np * 2;                         // trailing odd edge
        if (rem < e) {
            int2 cv = __ldg(&g_ecv[rem]);
            acc = fmaf(__int_as_float(cv.y), __ldg(&yin[cv.x * 16 + l]), acc);
        }
    }

    if (EP == 3) {
        float a0 = 0.f, a1 = 0.f, a2 = 0.f;
#pragma unroll
        for (int j = 0; j < 16; j++) {
            float d = __shfl_sync(0xffffffffu, acc, (lane & 16) + j);
            a0 = fmaf(d, Ws[j * 40 + l], a0);
            a1 = fmaf(d, Ws[j * 40 + l + 16], a1);
            if (l < 8) a2 = fmaf(d, Ws[j * 40 + l + 32], a2);
        }
        out[r * 40 + l]      = a0;
        out[r * 40 + l + 16] = a1;
        if (l < 8) out[r * 40 + l + 32] = a2;
    } else {
        float xr = fmaxf(acc, 0.f);
        float mn = xr, mx = xr;
#pragma unroll
        for (int o = 8; o > 0; o >>= 1) {
            mn = fminf(mn, __shfl_xor_sync(0xffffffffu, mn, o));
            mx = fmaxf(mx, __shfl_xor_sync(0xffffffffu, mx, o));
        }
        float dq;
        if (mx > mn) {
            float rs = QMAXF / (mx - mn);
            float nz = __ldg(&noise[r * 16 + l]);
            float q  = rintf((xr - mn) * rs + nz - 0.5f);
            q = fminf(fmaxf(q, 0.f), QMAXF);
            dq = q / rs + mn;
        } else dq = mn;

        if (EP == 2) {
            out[r * 16 + l] = dq;
        } else {
            float a = 0.f;
#pragma unroll
            for (int j = 0; j < 16; j++) {
                float d = __shfl_sync(0xffffffffu, dq, (lane & 16) + j);
                a = fmaf(d, Ws[j * 16 + l], a);
            }
            out[r * 16 + l] = a;
        }
    }
}

// ---------------------------------------------------------------------------
extern "C" void kernel_launch(void* const* d_in, const int* in_sizes, int n_in,
                              void* d_out, int out_size)
{
    const float* features = (const float*)d_in[0];
    const int*   row      = (const int*)  d_in[1];
    const int*   col      = (const int*)  d_in[2];
    const float* vals     = (const float*)d_in[3];
    const float* W1       = (const float*)d_in[4];
    const float* W2       = (const float*)d_in[5];
    const float* W3       = (const float*)d_in[6];
    const float* noise1   = (const float*)d_in[7];
    const float* noise2   = (const float*)d_in[8];
    const float* noise3   = (const float*)d_in[9];

    float *pya, *pyb;
    cudaGetSymbolAddress((void**)&pya, g_ya);
    cudaGetSymbolAddress((void**)&pyb, g_yb);

    const int nodeBlocks = (NN + 255) / 256;     // 391
    const int edgeBlocks = (NE + 255) / 256;     // 6250
    const int scanBlocks = (NN + 1023) / 1024;   // 98

    // CSR build
    k_clear  <<<nodeBlocks, 256>>>();
    k_hist   <<<edgeBlocks, 256>>>(row);
    k_scan1  <<<scanBlocks, 256>>>();
    k_scan3  <<<scanBlocks, 256>>>();
    k_scatter<<<edgeBlocks, 256>>>(row, col, vals);

    // Layer 1 dense front
    k_layer1<<<740, 128>>>(features, noise1, W1, pya);

    // SpMM pipeline (half-warp per row)
    k_spmm<1><<<NN / 16, 256>>>(pya, noise2, W2, pyb);
    k_spmm<2><<<NN / 16, 256>>>(pyb, noise3, nullptr, pya);
    k_spmm<3><<<NN / 16, 256>>>(pya, nullptr, W3, (float*)d_out);
}